// round 13
// baseline (speedup 1.0000x reference)
#include <cuda_runtime.h>
#include <cstdint>

// Problem constants (from reference):
//   B=256, P=4096, H=W=512
// Inputs (metadata order):
//   d_in[0]: indices   int32  [B, P, 2]   (JAX x64 disabled: jnp.int64 request -> int32)
//   d_in[1]: num_valid int32  [B]
//   d_in[2]: feats     float32[B, P, 1]
// Output: float32 [B, H, W]

#define B_  256
#define P_  4096
#define H_  512
#define W_  512
#define HW_ (H_ * W_)

#define THREADS_  512
#define PTS_PER_T (P_ / THREADS_)     // 8 prefetched points per thread
#define V8_PER_   (HW_ / 8)           // 32768 v8-stores per 1MB slice
#define ITERS_    (V8_PER_ / THREADS_) // 64... (32768/512 = 64)

// 256-bit zero store (Blackwell sm_100a): 1 instruction, 2 L1 wavefronts.
__device__ __forceinline__ void stg_v8_zero(float* p) {
    asm volatile(
        "st.global.v8.b32 [%0], {%1, %1, %1, %1, %1, %1, %1, %1};"
        :: "l"(p), "r"(0) : "memory");
}

__global__ __launch_bounds__(THREADS_, 2)
void scatter_densify_v8_kernel(const int* __restrict__ indices,
                               const int* __restrict__ num_valid,
                               const float* __restrict__ feats,
                               float* __restrict__ out)
{
    const int b = blockIdx.x;
    float* slice = out + (size_t)b * HW_;
    const int nv = num_valid[b];

    // ---- Prefetch scatter operands (hide reads under the fill stream) ----
    const int2*  ib = reinterpret_cast<const int2*>(indices) + (size_t)b * P_;
    const float* fb = feats + (size_t)b * P_;

    int2  rc[PTS_PER_T];
    float fv[PTS_PER_T];
    #pragma unroll
    for (int k = 0; k < PTS_PER_T; k++) {
        const int p = threadIdx.x + k * THREADS_;
        rc[k] = __ldg(ib + p);          // always in-bounds (P_ fully allocated)
        fv[k] = __ldg(fb + p);
    }

    // ---- Phase 1: zero this batch's 1MB slice with 256-bit stores ----
    // 32768 v8-stores / 512 threads = 64 iterations.
    float* base = slice + threadIdx.x * 8;
    #pragma unroll 8
    for (int i = 0; i < ITERS_; i++) {
        stg_v8_zero(base + i * (THREADS_ * 8));
    }
    __syncthreads();

    // ---- Phase 2: scatter-add prefetched points (RED, mostly L2 hits) ----
    #pragma unroll
    for (int k = 0; k < PTS_PER_T; k++) {
        const int p = threadIdx.x + k * THREADS_;
        if (p < nv) {
            const int r = rc[k].x;
            const int c = rc[k].y;
            if ((unsigned)r < H_ && (unsigned)c < W_) {
                atomicAdd(slice + r * W_ + c, fv[k]);
            }
        }
    }
}

extern "C" void kernel_launch(void* const* d_in, const int* in_sizes, int n_in,
                              void* d_out, int out_size)
{
    const int*   indices = (const int*)d_in[0];
    const int*   nvalid  = (const int*)d_in[1];
    const float* feats   = (const float*)d_in[2];
    float*       out     = (float*)d_out;

    scatter_densify_v8_kernel<<<B_, THREADS_>>>(indices, nvalid, feats, out);
}

// round 14
// speedup vs baseline: 1.0020x; 1.0020x over previous
#include <cuda_runtime.h>
#include <cstdint>

// Problem constants (from reference):
//   B=256, P=4096, H=W=512
// Inputs (metadata order):
//   d_in[0]: indices   int32  [B, P, 2]   (JAX x64 disabled: jnp.int64 request -> int32)
//   d_in[1]: num_valid int32  [B]
//   d_in[2]: feats     float32[B, P, 1]
// Output: float32 [B, H, W]

#define B_  256
#define P_  4096
#define H_  512
#define W_  512
#define HW_ (H_ * W_)

#define THREADS_  512
#define PTS_PER_T (P_ / THREADS_)       // 8 prefetched points per thread
#define V8_PER_   (HW_ / 8)             // 32768 v8-stores per 1MB slice
#define ITERS_    (V8_PER_ / THREADS_)  // 64 iterations

// 256-bit streaming zero store (Blackwell sm_100a): evict-first cache policy,
// matching what the driver's memset path uses for large fills.
__device__ __forceinline__ void stg_v8_zero_cs(float* p) {
    asm volatile(
        "st.global.cs.v8.b32 [%0], {%1, %1, %1, %1, %1, %1, %1, %1};"
        :: "l"(p), "r"(0) : "memory");
}

__global__ __launch_bounds__(THREADS_, 2)
void scatter_densify_cs_kernel(const int* __restrict__ indices,
                               const int* __restrict__ num_valid,
                               const float* __restrict__ feats,
                               float* __restrict__ out)
{
    const int b = blockIdx.x;
    float* slice = out + (size_t)b * HW_;
    const int nv = num_valid[b];

    // ---- Prefetch scatter operands (reads hide under the fill stream) ----
    const int2*  ib = reinterpret_cast<const int2*>(indices) + (size_t)b * P_;
    const float* fb = feats + (size_t)b * P_;

    int2  rc[PTS_PER_T];
    float fv[PTS_PER_T];
    #pragma unroll
    for (int k = 0; k < PTS_PER_T; k++) {
        const int p = threadIdx.x + k * THREADS_;
        rc[k] = __ldg(ib + p);          // always in-bounds (P_ fully allocated)
        fv[k] = __ldg(fb + p);
    }

    // ---- Phase 1: zero this batch's 1MB slice, streaming 256-bit stores ----
    float* base = slice + threadIdx.x * 8;
    #pragma unroll 8
    for (int i = 0; i < ITERS_; i++) {
        stg_v8_zero_cs(base + i * (THREADS_ * 8));
    }
    __syncthreads();

    // ---- Phase 2: scatter-add prefetched points (RED, L2-warm lines) ----
    #pragma unroll
    for (int k = 0; k < PTS_PER_T; k++) {
        const int p = threadIdx.x + k * THREADS_;
        if (p < nv) {
            const int r = rc[k].x;
            const int c = rc[k].y;
            if ((unsigned)r < H_ && (unsigned)c < W_) {
                atomicAdd(slice + r * W_ + c, fv[k]);
            }
        }
    }
}

extern "C" void kernel_launch(void* const* d_in, const int* in_sizes, int n_in,
                              void* d_out, int out_size)
{
    const int*   indices = (const int*)d_in[0];
    const int*   nvalid  = (const int*)d_in[1];
    const float* feats   = (const float*)d_in[2];
    float*       out     = (float*)d_out;

    scatter_densify_cs_kernel<<<B_, THREADS_>>>(indices, nvalid, feats, out);
}

// round 15
// speedup vs baseline: 1.0030x; 1.0010x over previous
#include <cuda_runtime.h>
#include <cstdint>

// Problem constants (from reference):
//   B=256, P=4096, H=W=512
// Inputs (metadata order):
//   d_in[0]: indices   int32  [B, P, 2]   (JAX x64 disabled: jnp.int64 request -> int32)
//   d_in[1]: num_valid int32  [B]
//   d_in[2]: feats     float32[B, P, 1]
// Output: float32 [B, H, W]

#define B_  256
#define P_  4096
#define H_  512
#define W_  512
#define HW_ (H_ * W_)

#define THREADS_    512
#define PTS_PER_T   (P_ / THREADS_)         // 8 prefetched points per thread
#define SMEM_BYTES  32768                   // 32 KB zero staging buffer
#define SLICE_BYTES (HW_ * 4)               // 1 MB per batch
#define HALF_BYTES  (SLICE_BYTES / 2)       // 512 KB per engine
#define N_TMA       (HALF_BYTES / SMEM_BYTES)       // 16 bulk stores (upper half)
#define STG_V8_N    (HALF_BYTES / 32)               // 16384 v8 stores (lower half)
#define STG_ITERS   (STG_V8_N / THREADS_)           // 32 iterations

__device__ __forceinline__ uint32_t smem_u32(const void* p) {
    uint32_t a;
    asm("{ .reg .u64 t; cvta.to.shared.u64 t, %1; cvt.u32.u64 %0, t; }"
        : "=r"(a) : "l"(p));
    return a;
}

__device__ __forceinline__ void stg_v8_zero(float* p) {
    asm volatile(
        "st.global.v8.b32 [%0], {%1, %1, %1, %1, %1, %1, %1, %1};"
        :: "l"(p), "r"(0) : "memory");
}

__global__ __launch_bounds__(THREADS_, 2)
void scatter_densify_hybrid_kernel(const int* __restrict__ indices,
                                   const int* __restrict__ num_valid,
                                   const float* __restrict__ feats,
                                   float* __restrict__ out)
{
    __shared__ __align__(128) float4 zbuf[SMEM_BYTES / 16];

    const int b = blockIdx.x;
    float* slice = out + (size_t)b * HW_;
    const int nv = num_valid[b];

    // ---- Prefetch scatter operands (reads hide under the fill stream) ----
    const int2*  ib = reinterpret_cast<const int2*>(indices) + (size_t)b * P_;
    const float* fb = feats + (size_t)b * P_;

    int2  rc[PTS_PER_T];
    float fv[PTS_PER_T];
    #pragma unroll
    for (int k = 0; k < PTS_PER_T; k++) {
        const int p = threadIdx.x + k * THREADS_;
        rc[k] = __ldg(ib + p);          // always in-bounds (P_ fully allocated)
        fv[k] = __ldg(fb + p);
    }

    // ---- Zero the SMEM staging buffer (TMA source) ----
    const float4 z4 = make_float4(0.f, 0.f, 0.f, 0.f);
    #pragma unroll
    for (int i = threadIdx.x; i < SMEM_BYTES / 16; i += THREADS_) {
        zbuf[i] = z4;
    }
    __syncthreads();

    // ---- Hybrid fill: TMA engine covers upper 512 KB, warps cover lower ----
    if (threadIdx.x == 0) {
        asm volatile("fence.proxy.async.shared::cta;" ::: "memory");
        const uint32_t src = smem_u32(zbuf);
        char* dst = reinterpret_cast<char*>(slice) + HALF_BYTES;
        #pragma unroll
        for (int c = 0; c < N_TMA; c++) {
            asm volatile(
                "cp.async.bulk.global.shared::cta.bulk_group [%0], [%1], %2;"
                :: "l"(dst + (size_t)c * SMEM_BYTES), "r"(src), "n"(SMEM_BYTES)
                : "memory");
        }
        asm volatile("cp.async.bulk.commit_group;" ::: "memory");
    }

    // Lower 512 KB via 256-bit stores: 16384 v8-stores / 512 threads = 32 iters.
    {
        float* base = slice + threadIdx.x * 8;
        #pragma unroll 8
        for (int i = 0; i < STG_ITERS; i++) {
            stg_v8_zero(base + i * (THREADS_ * 8));
        }
    }

    if (threadIdx.x == 0) {
        asm volatile("cp.async.bulk.wait_group 0;" ::: "memory");
    }
    __syncthreads();   // both halves of the zero-fill complete & visible

    // ---- Scatter-add prefetched points (RED, L2-warm lines) ----
    #pragma unroll
    for (int k = 0; k < PTS_PER_T; k++) {
        const int p = threadIdx.x + k * THREADS_;
        if (p < nv) {
            const int r = rc[k].x;
            const int c = rc[k].y;
            if ((unsigned)r < H_ && (unsigned)c < W_) {
                atomicAdd(slice + r * W_ + c, fv[k]);
            }
        }
    }
}

extern "C" void kernel_launch(void* const* d_in, const int* in_sizes, int n_in,
                              void* d_out, int out_size)
{
    const int*   indices = (const int*)d_in[0];
    const int*   nvalid  = (const int*)d_in[1];
    const float* feats   = (const float*)d_in[2];
    float*       out     = (float*)d_out;

    scatter_densify_hybrid_kernel<<<B_, THREADS_>>>(indices, nvalid, feats, out);
}